// round 12
// baseline (speedup 1.0000x reference)
#include <cuda_runtime.h>

// Effective weights: w_eff_m[u] = sum_v W_lin_m[u,v] * W_tp_m[v], pre-scaled.
// s0 = lin_norm*alpha = 1/(16*sqrt(768)); s1 = s0/sqrt(3); s2 = s0/sqrt(5)
__device__ float g_w[3 * 256];

#define S0 0.0022552744890219763f
#define S1 0.0013020833333333333f
#define S2 0.0010085837883053976f

// One warp per output row u (768 rows): 96 blocks x 8 warps.
__global__ void __launch_bounds__(256)
prep_weights_kernel(const float* __restrict__ W0,
                    const float* __restrict__ W1,
                    const float* __restrict__ W2,
                    const float* __restrict__ T0,
                    const float* __restrict__ T1,
                    const float* __restrict__ T2) {
    int gw = blockIdx.x * 8 + (threadIdx.x >> 5);   // u index 0..767
    int lane = threadIdx.x & 31;
    int m = gw >> 8;
    int u = gw & 255;

    const float* W = (m == 0) ? W0 : (m == 1) ? W1 : W2;
    const float* T = (m == 0) ? T0 : (m == 1) ? T1 : T2;
    float scale = (m == 0) ? S0 : (m == 1) ? S1 : S2;

    const float4* row4 = (const float4*)(W + (size_t)u * 256) + lane * 2;
    const float4* t4   = (const float4*)T + lane * 2;

    float4 r0 = row4[0], r1 = row4[1];
    float4 w0 = t4[0],   w1 = t4[1];

    float acc = r0.x * w0.x + r0.y * w0.y + r0.z * w0.z + r0.w * w0.w
              + r1.x * w1.x + r1.y * w1.y + r1.z * w1.z + r1.w * w1.w;
#pragma unroll
    for (int off = 16; off; off >>= 1)
        acc += __shfl_xor_sync(0xffffffffu, acc, off);
    if (lane == 0) g_w[m * 256 + u] = acc * scale;
}

// One balanced wave: grid = 592 = 148 SMs x 4 CTAs. Each block owns a
// contiguous node range (<=128 nodes). Charges staged in SMEM once. Hot loop
// is barrier-free: 2 nodes/iter, front-batched float4 streaming loads,
// weight(reg) x charge(SMEM select) FMAs, then only a 2-LEVEL shuffle
// reduce (dependent tail ~55cy instead of ~130cy) and 8 partials stored per
// warp per node (lanes 0-7, conflict-free STS). After the loop: single
// barrier, tail sums the 64 partials per node, plain STG to out.
__global__ void __launch_bounds__(256, 4)
energy_kernel(const float* __restrict__ nf,
              const float* __restrict__ ch,
              float* __restrict__ out, int n, int nblk) {
    __shared__ float cbuf[128 * 9];
    __shared__ float part[128][64];   // [node][warp*8 + group]

    long base = (long)blockIdx.x * n / nblk;
    long end  = (long)(blockIdx.x + 1) * n / nblk;
    int cnt = (int)(end - base);
    if (cnt <= 0) return;

    int t = threadIdx.x;
    int warp = t >> 5;
    int lane = t & 31;

    // Per-thread element metadata (fixed):
    // slot A: float4 q = t        -> j = 4t+e            (x0 if t<64 else x1)
    // slot B: float4 q = t + 256  -> j = 1024 + 4t + e   (x2)
    // slot C: float4 q = t + 512  -> j = 2048 + 4t + e   (x2, t<64 only)
    float aA[4], aB[4], aC[4];
    int kA[4], kB[4], kC[4];
#pragma unroll
    for (int e = 0; e < 4; e++) {
        int jA = 4 * t + e;
        if (jA < 256) { aA[e] = g_w[jA]; kA[e] = 0; }
        else { int r = jA - 256; aA[e] = g_w[256 + r / 3]; kA[e] = 1 + r % 3; }
        int rB = 4 * t + e;
        aB[e] = g_w[512 + rB / 5]; kB[e] = 4 + rB % 5;
        int rC = 1024 + 4 * t + e;
        if (t < 64) { aC[e] = g_w[512 + rC / 5]; kC[e] = 4 + rC % 5; }
        else        { aC[e] = 0.f; kC[e] = 0; }
    }

    // Stage this block's charges once.
    {
        int total = cnt * 9;
        const float* cp = ch + base * 9;
        for (int i = t; i < total; i += 256) cbuf[i] = __ldg(cp + i);
    }
    __syncthreads();

    for (int loc = 0; loc < cnt; loc += 2) {
        const float4* p0 = (const float4*)(nf + (base + loc) * 2304);
        const float4* p1 = p0 + 576;

        float4 Z = make_float4(0.f, 0.f, 0.f, 0.f);
        float4 A0 = __ldcs(p0 + t), B0 = __ldcs(p0 + 256 + t);
        float4 C0 = Z, A1 = Z, B1 = Z, C1 = Z;
        bool v1 = (loc + 1) < cnt;
        if (t < 64) C0 = __ldcs(p0 + 512 + t);
        if (v1) {
            A1 = __ldcs(p1 + t); B1 = __ldcs(p1 + 256 + t);
            if (t < 64) C1 = __ldcs(p1 + 512 + t);
        }

        const float* cb0 = cbuf + 9 * loc;
        const float* cb1 = cb0 + 9;

        float acc0, acc1;
        if (t < 64) {
            acc0 = cb0[0] * (A0.x * aA[0] + A0.y * aA[1] + A0.z * aA[2] + A0.w * aA[3]);
            acc1 = cb1[0] * (A1.x * aA[0] + A1.y * aA[1] + A1.z * aA[2] + A1.w * aA[3]);
#pragma unroll
            for (int e = 0; e < 4; e++) {
                acc0 = fmaf((&C0.x)[e], aC[e] * cb0[kC[e]], acc0);
                acc1 = fmaf((&C1.x)[e], aC[e] * cb1[kC[e]], acc1);
            }
        } else {
            acc0 = 0.f; acc1 = 0.f;
#pragma unroll
            for (int e = 0; e < 4; e++) {
                acc0 = fmaf((&A0.x)[e], aA[e] * cb0[kA[e]], acc0);
                acc1 = fmaf((&A1.x)[e], aA[e] * cb1[kA[e]], acc1);
            }
        }
#pragma unroll
        for (int e = 0; e < 4; e++) {
            acc0 = fmaf((&B0.x)[e], aB[e] * cb0[kB[e]], acc0);
            acc1 = fmaf((&B1.x)[e], aB[e] * cb1[kB[e]], acc1);
        }

        // 2-level interleaved shuffle reduce: lane l ends with the sum of
        // lanes {l, l^8, l^16, l^24}; lanes 0-7 hold the 8 group sums.
        acc0 += __shfl_xor_sync(0xffffffffu, acc0, 16);
        acc1 += __shfl_xor_sync(0xffffffffu, acc1, 16);
        acc0 += __shfl_xor_sync(0xffffffffu, acc0, 8);
        acc1 += __shfl_xor_sync(0xffffffffu, acc1, 8);

        if (lane < 8) {
            part[loc][warp * 8 + lane] = acc0;
            if (v1) part[loc + 1][warp * 8 + lane] = acc1;
        }
    }

    __syncthreads();

    // Tail: thread t (< cnt) sums the 64 partials for node t.
    if (t < cnt) {
        const float4* q = (const float4*)part[t];
        float4 s0 = q[0], s1 = q[1], s2 = q[2], s3 = q[3];
        float4 s4 = q[4], s5 = q[5], s6 = q[6], s7 = q[7];
        float4 u0 = q[8], u1 = q[9], u2 = q[10], u3 = q[11];
        float4 u4 = q[12], u5 = q[13], u6 = q[14], u7 = q[15];
        float s = (s0.x + s0.y + s0.z + s0.w) + (s1.x + s1.y + s1.z + s1.w)
                + (s2.x + s2.y + s2.z + s2.w) + (s3.x + s3.y + s3.z + s3.w)
                + (s4.x + s4.y + s4.z + s4.w) + (s5.x + s5.y + s5.z + s5.w)
                + (s6.x + s6.y + s6.z + s6.w) + (s7.x + s7.y + s7.z + s7.w)
                + (u0.x + u0.y + u0.z + u0.w) + (u1.x + u1.y + u1.z + u1.w)
                + (u2.x + u2.y + u2.z + u2.w) + (u3.x + u3.y + u3.z + u3.w)
                + (u4.x + u4.y + u4.z + u4.w) + (u5.x + u5.y + u5.z + u5.w)
                + (u6.x + u6.y + u6.z + u6.w) + (u7.x + u7.y + u7.z + u7.w);
        out[base + t] = s;
    }
}

extern "C" void kernel_launch(void* const* d_in, const int* in_sizes, int n_in,
                              void* d_out, int out_size) {
    const float* node_feats = (const float*)d_in[0];
    const float* charges    = (const float*)d_in[1];
    const float* W_lin0     = (const float*)d_in[2];
    const float* W_lin1     = (const float*)d_in[3];
    const float* W_lin2     = (const float*)d_in[4];
    const float* W_tp0      = (const float*)d_in[5];
    const float* W_tp1      = (const float*)d_in[6];
    const float* W_tp2      = (const float*)d_in[7];
    float* out = (float*)d_out;

    int n = in_sizes[1] / 9;   // number of nodes

    prep_weights_kernel<<<96, 256>>>(W_lin0, W_lin1, W_lin2,
                                     W_tp0, W_tp1, W_tp2);

    // One balanced wave: 148 SMs x 4 CTAs/SM. Guarantee <=128 nodes/block.
    int nblk = 592;
    int minblk = (n + 127) / 128;
    if (minblk > nblk) nblk = minblk;
    energy_kernel<<<nblk, 256>>>(node_feats, charges, out, n, nblk);
}

// round 13
// speedup vs baseline: 1.0238x; 1.0238x over previous
#include <cuda_runtime.h>

// Effective weights: w_eff_m[u] = sum_v W_lin_m[u,v] * W_tp_m[v], pre-scaled.
// s0 = lin_norm*alpha = 1/(16*sqrt(768)); s1 = s0/sqrt(3); s2 = s0/sqrt(5)
__device__ float g_w[3 * 256];

#define S0 0.0022552744890219763f
#define S1 0.0013020833333333333f
#define S2 0.0010085837883053976f

// One warp per output row u (768 rows): 192 blocks x 4 warps (wide spread,
// latency-bound, ~1-2us).
__global__ void __launch_bounds__(128)
prep_weights_kernel(const float* __restrict__ W0,
                    const float* __restrict__ W1,
                    const float* __restrict__ W2,
                    const float* __restrict__ T0,
                    const float* __restrict__ T1,
                    const float* __restrict__ T2) {
    int gw = blockIdx.x * 4 + (threadIdx.x >> 5);   // u index 0..767
    int lane = threadIdx.x & 31;
    int m = gw >> 8;
    int u = gw & 255;

    const float* W = (m == 0) ? W0 : (m == 1) ? W1 : W2;
    const float* T = (m == 0) ? T0 : (m == 1) ? T1 : T2;
    float scale = (m == 0) ? S0 : (m == 1) ? S1 : S2;

    const float4* row4 = (const float4*)(W + (size_t)u * 256) + lane * 2;
    const float4* t4   = (const float4*)T + lane * 2;

    float4 r0 = row4[0], r1 = row4[1];
    float4 w0 = t4[0],   w1 = t4[1];

    float acc = r0.x * w0.x + r0.y * w0.y + r0.z * w0.z + r0.w * w0.w
              + r1.x * w1.x + r1.y * w1.y + r1.z * w1.z + r1.w * w1.w;
#pragma unroll
    for (int off = 16; off; off >>= 1)
        acc += __shfl_xor_sync(0xffffffffu, acc, off);
    if (lane == 0) g_w[m * 256 + u] = acc * scale;
}

// Best-measured structure (main 94.5us @ 81.5% DRAM, regs=64, 4 CTAs/SM):
// One balanced wave: grid = 592 = 148 SMs x 4 CTAs. Each block owns a
// contiguous node range (<=128 nodes). Charges staged in SMEM once. Hot loop
// is barrier-free: 2 nodes/iter, front-batched float4 streaming loads,
// weight(reg) x charge(SMEM select) FMAs, interleaved 5-level shuffle
// reduce, one STS per warp per node. After the loop: single barrier,
// coalesced tail sum of the 8 warp partials, plain STG to out (no zero-init
// needed, no atomics).
__global__ void __launch_bounds__(256, 4)
energy_kernel(const float* __restrict__ nf,
              const float* __restrict__ ch,
              float* __restrict__ out, int n, int nblk) {
    __shared__ float cbuf[128 * 9];
    __shared__ float part[8][128];

    long base = (long)blockIdx.x * n / nblk;
    long end  = (long)(blockIdx.x + 1) * n / nblk;
    int cnt = (int)(end - base);
    if (cnt <= 0) return;

    int t = threadIdx.x;
    int warp = t >> 5;
    int lane = t & 31;

    // Per-thread element metadata (fixed):
    // slot A: float4 q = t        -> j = 4t+e            (x0 if t<64 else x1)
    // slot B: float4 q = t + 256  -> j = 1024 + 4t + e   (x2)
    // slot C: float4 q = t + 512  -> j = 2048 + 4t + e   (x2, t<64 only)
    float aA[4], aB[4], aC[4];
    int kA[4], kB[4], kC[4];
#pragma unroll
    for (int e = 0; e < 4; e++) {
        int jA = 4 * t + e;
        if (jA < 256) { aA[e] = g_w[jA]; kA[e] = 0; }
        else { int r = jA - 256; aA[e] = g_w[256 + r / 3]; kA[e] = 1 + r % 3; }
        int rB = 4 * t + e;
        aB[e] = g_w[512 + rB / 5]; kB[e] = 4 + rB % 5;
        int rC = 1024 + 4 * t + e;
        if (t < 64) { aC[e] = g_w[512 + rC / 5]; kC[e] = 4 + rC % 5; }
        else        { aC[e] = 0.f; kC[e] = 0; }
    }

    // Stage this block's charges once.
    {
        int total = cnt * 9;
        const float* cp = ch + base * 9;
        for (int i = t; i < total; i += 256) cbuf[i] = __ldg(cp + i);
    }
    __syncthreads();

    for (int loc = 0; loc < cnt; loc += 2) {
        const float4* p0 = (const float4*)(nf + (base + loc) * 2304);
        const float4* p1 = p0 + 576;

        float4 Z = make_float4(0.f, 0.f, 0.f, 0.f);
        float4 A0 = __ldcs(p0 + t), B0 = __ldcs(p0 + 256 + t);
        float4 C0 = Z, A1 = Z, B1 = Z, C1 = Z;
        bool v1 = (loc + 1) < cnt;
        if (t < 64) C0 = __ldcs(p0 + 512 + t);
        if (v1) {
            A1 = __ldcs(p1 + t); B1 = __ldcs(p1 + 256 + t);
            if (t < 64) C1 = __ldcs(p1 + 512 + t);
        }

        const float* cb0 = cbuf + 9 * loc;
        const float* cb1 = cb0 + 9;

        float acc0, acc1;
        if (t < 64) {
            acc0 = cb0[0] * (A0.x * aA[0] + A0.y * aA[1] + A0.z * aA[2] + A0.w * aA[3]);
            acc1 = cb1[0] * (A1.x * aA[0] + A1.y * aA[1] + A1.z * aA[2] + A1.w * aA[3]);
#pragma unroll
            for (int e = 0; e < 4; e++) {
                acc0 = fmaf((&C0.x)[e], aC[e] * cb0[kC[e]], acc0);
                acc1 = fmaf((&C1.x)[e], aC[e] * cb1[kC[e]], acc1);
            }
        } else {
            acc0 = 0.f; acc1 = 0.f;
#pragma unroll
            for (int e = 0; e < 4; e++) {
                acc0 = fmaf((&A0.x)[e], aA[e] * cb0[kA[e]], acc0);
                acc1 = fmaf((&A1.x)[e], aA[e] * cb1[kA[e]], acc1);
            }
        }
#pragma unroll
        for (int e = 0; e < 4; e++) {
            acc0 = fmaf((&B0.x)[e], aB[e] * cb0[kB[e]], acc0);
            acc1 = fmaf((&B1.x)[e], aB[e] * cb1[kB[e]], acc1);
        }

        // Interleaved warp reductions (two independent chains).
#pragma unroll
        for (int off = 16; off; off >>= 1) {
            acc0 += __shfl_xor_sync(0xffffffffu, acc0, off);
            acc1 += __shfl_xor_sync(0xffffffffu, acc1, off);
        }

        if (lane == 0) {
            part[warp][loc] = acc0;
            if (v1) part[warp][loc + 1] = acc1;
        }
    }

    __syncthreads();

    // Coalesced tail: thread t (< cnt) sums the 8 warp partials for node t.
    if (t < cnt) {
        float s = part[0][t] + part[1][t] + part[2][t] + part[3][t]
                + part[4][t] + part[5][t] + part[6][t] + part[7][t];
        out[base + t] = s;
    }
}

extern "C" void kernel_launch(void* const* d_in, const int* in_sizes, int n_in,
                              void* d_out, int out_size) {
    const float* node_feats = (const float*)d_in[0];
    const float* charges    = (const float*)d_in[1];
    const float* W_lin0     = (const float*)d_in[2];
    const float* W_lin1     = (const float*)d_in[3];
    const float* W_lin2     = (const float*)d_in[4];
    const float* W_tp0      = (const float*)d_in[5];
    const float* W_tp1      = (const float*)d_in[6];
    const float* W_tp2      = (const float*)d_in[7];
    float* out = (float*)d_out;

    int n = in_sizes[1] / 9;   // number of nodes

    prep_weights_kernel<<<192, 128>>>(W_lin0, W_lin1, W_lin2,
                                      W_tp0, W_tp1, W_tp2);

    // One balanced wave: 148 SMs x 4 CTAs/SM. Guarantee <=128 nodes/block.
    int nblk = 592;
    int minblk = (n + 127) / 128;
    if (minblk > nblk) nblk = minblk;
    energy_kernel<<<nblk, 256>>>(node_feats, charges, out, n, nblk);
}